// round 15
// baseline (speedup 1.0000x reference)
#include <cuda_runtime.h>
#include <cuda_fp16.h>
#include <math.h>

#define BB 16
#define SS 1024
#define DD 1024
#define HH 16
#define DH 64

// Device scratch (no allocations allowed). All-fp16 pipeline:
__device__ __half g_qh[BB * HH * SS * DH];  // Q * 0.125, fp16, head-split
__device__ __half g_kh[BB * HH * SS * DH];  // K fp16
__device__ __half g_vh[BB * HH * SS * DH];  // V fp16
__device__ __half g_xh[BB * SS * DD];       // fp16 X
__device__ __half g_wh[3 * DD * DD];        // fp16 Wq,Wk,Wv

// ---------------------------------------------------------------------------
__device__ __forceinline__ void mma_f16(float* d, const unsigned* a, const unsigned* b) {
    asm volatile(
        "mma.sync.aligned.m16n8k16.row.col.f32.f16.f16.f32 "
        "{%0,%1,%2,%3},{%4,%5,%6,%7},{%8,%9},{%0,%1,%2,%3};"
        : "+f"(d[0]), "+f"(d[1]), "+f"(d[2]), "+f"(d[3])
        : "r"(a[0]), "r"(a[1]), "r"(a[2]), "r"(a[3]), "r"(b[0]), "r"(b[1]));
}

__device__ __forceinline__ unsigned h2u(__half2 h) {
    return *(unsigned*)&h;
}

// ---------------------------------------------------------------------------
// Pre-pass: fp32 -> fp16 (rn), 8 elements per thread.
// ---------------------------------------------------------------------------
__global__ void to_half(__half* __restrict__ dst, const float* __restrict__ src, int n8)
{
    int i = blockIdx.x * blockDim.x + threadIdx.x;
    if (i < n8) {
        float4 a = ((const float4*)src)[2 * i];
        float4 b = ((const float4*)src)[2 * i + 1];
        uint4 u;
        u.x = h2u(__floats2half2_rn(a.x, a.y));
        u.y = h2u(__floats2half2_rn(a.z, a.w));
        u.z = h2u(__floats2half2_rn(b.x, b.y));
        u.w = h2u(__floats2half2_rn(b.z, b.w));
        ((uint4*)dst)[i] = u;
    }
}

// ---------------------------------------------------------------------------
// QKV projection: Yh = fp16((X @ W^T + b) * scale), head-split store.
// R11/R13-proven loop cadence; fp16 source and fp16 output.
// BM=BN=128, BK=32, 256 thr (8 warps 4x2), warp tile 32x64.
// ---------------------------------------------------------------------------
__global__ __launch_bounds__(256)
void qkv_gemm(const float* __restrict__ bias, int which)
{
    __shared__ __half sa[128][40];   // [m][k]
    __shared__ __half sb[128][40];   // [n][k]

    __half* __restrict__ Yh = (which == 0) ? g_qh : (which == 1) ? g_kh : g_vh;
    const __half* __restrict__ Xh = g_xh;
    const __half* __restrict__ Wh = g_wh + (size_t)which * DD * DD;
    const float scale = (which == 0) ? 0.125f : 1.0f;

    const int tid  = threadIdx.x;
    const int lane = tid & 31;
    const int warp = tid >> 5;
    const int wm   = (warp & 3) * 32;
    const int wn   = (warp >> 2) * 64;
    const int m0   = blockIdx.y * 128;
    const int n0   = blockIdx.x * 128;

    const int lr = tid >> 3;        // 0..31
    const int lc = (tid & 7) * 4;   // half cols 0,4,...,28

    const int r4 = lane >> 2;
    const int c4 = lane & 3;

    float acc[2][8][4];
    #pragma unroll
    for (int i = 0; i < 2; i++)
        #pragma unroll
        for (int j = 0; j < 8; j++)
            #pragma unroll
            for (int c = 0; c < 4; c++) acc[i][j][c] = 0.0f;

    for (int k0 = 0; k0 < DD; k0 += 32) {
        uint2 ua[4], ub[4];
        #pragma unroll
        for (int i = 0; i < 4; i++) {
            ua[i] = *(const uint2*)(Xh + (size_t)(m0 + lr + 32 * i) * DD + k0 + lc);
            ub[i] = *(const uint2*)(Wh + (size_t)(n0 + lr + 32 * i) * DD + k0 + lc);
        }
        __syncthreads();
        #pragma unroll
        for (int i = 0; i < 4; i++) {
            *(uint2*)&sa[lr + 32 * i][lc] = ua[i];
            *(uint2*)&sb[lr + 32 * i][lc] = ub[i];
        }
        __syncthreads();

        #pragma unroll
        for (int ks = 0; ks < 2; ks++) {
            const int kk = ks * 16 + 2 * c4;
            unsigned af[2][4];
            #pragma unroll
            for (int mt = 0; mt < 2; mt++) {
                const int rb = wm + mt * 16;
                af[mt][0] = *(const unsigned*)&sa[rb + r4    ][kk    ];
                af[mt][1] = *(const unsigned*)&sa[rb + r4 + 8][kk    ];
                af[mt][2] = *(const unsigned*)&sa[rb + r4    ][kk + 8];
                af[mt][3] = *(const unsigned*)&sa[rb + r4 + 8][kk + 8];
            }
            #pragma unroll
            for (int nt = 0; nt < 8; nt++) {
                const int cb = wn + nt * 8;
                unsigned bf[2];
                bf[0] = *(const unsigned*)&sb[cb + r4][kk    ];
                bf[1] = *(const unsigned*)&sb[cb + r4][kk + 8];
                mma_f16(acc[0][nt], af[0], bf);
                mma_f16(acc[1][nt], af[1], bf);
            }
        }
    }

    // Epilogue: fp16((acc + bias) * scale), head-split scatter.
    #pragma unroll
    for (int mt = 0; mt < 2; mt++) {
        const int mA = m0 + wm + mt * 16 + r4;
        const int mB = mA + 8;
        const int bA = mA >> 10, sA_ = mA & 1023;
        const int bB = mB >> 10, sB_ = mB & 1023;
        #pragma unroll
        for (int nt = 0; nt < 8; nt++) {
            const int col = n0 + wn + nt * 8 + 2 * c4;
            const int h = col >> 6, d = col & 63;
            const float b0 = bias[col], b1 = bias[col + 1];
            unsigned vA = h2u(__floats2half2_rn((acc[mt][nt][0] + b0) * scale,
                                                (acc[mt][nt][1] + b1) * scale));
            unsigned vB = h2u(__floats2half2_rn((acc[mt][nt][2] + b0) * scale,
                                                (acc[mt][nt][3] + b1) * scale));
            *(unsigned*)(Yh + (((size_t)(bA * HH + h) * SS + sA_) * DH) + d) = vA;
            *(unsigned*)(Yh + (((size_t)(bB * HH + h) * SS + sB_) * DH) + d) = vB;
        }
    }
}

// ---------------------------------------------------------------------------
// Flash attention, fp16 mma, BC=64 (R13 structure). fp16 Q/K/V inputs:
// Q/K staging = pure copy; V staging = fp16 load + byte_perm interleave.
// Block = 128 thr (4 warps), 16 q-rows per warp, Dh=64.
// ---------------------------------------------------------------------------
__global__ __launch_bounds__(128)
void attn_kernel(float* __restrict__ out)
{
    __shared__ __half sk[64][72];
    __shared__ unsigned sv2[32][72];
    __shared__ __half sp[4][16][72];

    const int tid  = threadIdx.x;
    const int lane = tid & 31;
    const int warp = tid >> 5;
    const int bh   = blockIdx.y;
    const int b    = bh >> 4;
    const int h    = bh & 15;
    const int qrow0 = blockIdx.x * 64 + warp * 16;

    const int r4 = lane >> 2;
    const int c4 = lane & 3;

    const __half* Qh = g_qh + (size_t)bh * SS * DH;
    const __half* Kh = g_kh + (size_t)bh * SS * DH;
    const __half* Vh = g_vh + (size_t)bh * SS * DH;

    // stage Q (already scaled, fp16): pure copy into sp[warp]
    {
        #pragma unroll
        for (int i = 0; i < 4; i++) {
            const int idx = lane + i * 32;          // 0..127
            const int row = idx >> 3;               // 0..15
            const int cc  = (idx & 7) * 8;
            uint4 t = *(const uint4*)(Qh + (size_t)(qrow0 + row) * DH + cc);
            *(uint4*)&sp[warp][row][cc] = t;
        }
    }
    __syncwarp();
    unsigned qa[4][4];
    #pragma unroll
    for (int ks = 0; ks < 4; ks++) {
        const int kk = ks * 16 + 2 * c4;
        qa[ks][0] = *(const unsigned*)&sp[warp][r4    ][kk    ];
        qa[ks][1] = *(const unsigned*)&sp[warp][r4 + 8][kk    ];
        qa[ks][2] = *(const unsigned*)&sp[warp][r4    ][kk + 8];
        qa[ks][3] = *(const unsigned*)&sp[warp][r4 + 8][kk + 8];
    }
    __syncwarp();

    float o[8][4];
    #pragma unroll
    for (int nt = 0; nt < 8; nt++)
        #pragma unroll
        for (int c = 0; c < 4; c++) o[nt][c] = 0.0f;
    float m0v = -INFINITY, m1v = -INFINITY;
    float l0 = 0.0f, l1 = 0.0f;

    for (int t0 = 0; t0 < SS; t0 += 64) {
        __syncthreads();
        // K: 64 rows x 64 halfs: pure copy, 4 x uint4 per thread
        #pragma unroll
        for (int i = 0; i < 4; i++) {
            const int idx = tid + i * 128;          // 0..511
            const int row = idx >> 3;               // 0..63
            const int cc  = (idx & 7) * 8;
            uint4 t = *(const uint4*)(Kh + (size_t)(t0 + row) * DH + cc);
            *(uint4*)&sk[row][cc] = t;
        }
        // V: 32 kv-pairs; fp16 loads + byte_perm interleave
        {
            const int kvp = tid >> 2;               // 0..31
            const int d0  = (tid & 3) * 16;         // 0,16,32,48
            const __half* v0 = Vh + (size_t)(t0 + 2 * kvp) * DH + d0;
            const __half* v1 = v0 + DH;
            uint4 A0 = *(const uint4*)(v0);
            uint4 A1 = *(const uint4*)(v0 + 8);
            uint4 B0 = *(const uint4*)(v1);
            uint4 B1 = *(const uint4*)(v1 + 8);
            uint4 w;
            w.x = __byte_perm(A0.x, B0.x, 0x5410);
            w.y = __byte_perm(A0.x, B0.x, 0x7632);
            w.z = __byte_perm(A0.y, B0.y, 0x5410);
            w.w = __byte_perm(A0.y, B0.y, 0x7632);
            *(uint4*)&sv2[kvp][d0] = w;
            w.x = __byte_perm(A0.z, B0.z, 0x5410);
            w.y = __byte_perm(A0.z, B0.z, 0x7632);
            w.z = __byte_perm(A0.w, B0.w, 0x5410);
            w.w = __byte_perm(A0.w, B0.w, 0x7632);
            *(uint4*)&sv2[kvp][d0 + 4] = w;
            w.x = __byte_perm(A1.x, B1.x, 0x5410);
            w.y = __byte_perm(A1.x, B1.x, 0x7632);
            w.z = __byte_perm(A1.y, B1.y, 0x5410);
            w.w = __byte_perm(A1.y, B1.y, 0x7632);
            *(uint4*)&sv2[kvp][d0 + 8] = w;
            w.x = __byte_perm(A1.z, B1.z, 0x5410);
            w.y = __byte_perm(A1.z, B1.z, 0x7632);
            w.z = __byte_perm(A1.w, B1.w, 0x5410);
            w.w = __byte_perm(A1.w, B1.w, 0x7632);
            *(uint4*)&sv2[kvp][d0 + 12] = w;
        }
        __syncthreads();

        // S = Q @ K^T : 8 kv n-tiles x 4 k16 steps
        float s[8][4];
        #pragma unroll
        for (int nt = 0; nt < 8; nt++) {
            #pragma unroll
            for (int c = 0; c < 4; c++) s[nt][c] = 0.0f;
            #pragma unroll
            for (int ks = 0; ks < 4; ks++) {
                const int kk = ks * 16 + 2 * c4;
                unsigned bf[2];
                bf[0] = *(const unsigned*)&sk[nt * 8 + r4][kk    ];
                bf[1] = *(const unsigned*)&sk[nt * 8 + r4][kk + 8];
                mma_f16(s[nt], qa[ks], bf);
            }
        }

        // online softmax (fp32)
        float tm0 = -INFINITY, tm1 = -INFINITY;
        #pragma unroll
        for (int nt = 0; nt < 8; nt++) {
            tm0 = fmaxf(tm0, fmaxf(s[nt][0], s[nt][1]));
            tm1 = fmaxf(tm1, fmaxf(s[nt][2], s[nt][3]));
        }
        tm0 = fmaxf(tm0, __shfl_xor_sync(0xffffffffu, tm0, 1));
        tm0 = fmaxf(tm0, __shfl_xor_sync(0xffffffffu, tm0, 2));
        tm1 = fmaxf(tm1, __shfl_xor_sync(0xffffffffu, tm1, 1));
        tm1 = fmaxf(tm1, __shfl_xor_sync(0xffffffffu, tm1, 2));

        const float mn0 = fmaxf(m0v, tm0);
        const float mn1 = fmaxf(m1v, tm1);
        const float sc0 = __expf(m0v - mn0);
        const float sc1 = __expf(m1v - mn1);
        m0v = mn0; m1v = mn1;

        float ps0 = 0.0f, ps1 = 0.0f;
        #pragma unroll
        for (int nt = 0; nt < 8; nt++) {
            s[nt][0] = __expf(s[nt][0] - mn0);
            s[nt][1] = __expf(s[nt][1] - mn0);
            s[nt][2] = __expf(s[nt][2] - mn1);
            s[nt][3] = __expf(s[nt][3] - mn1);
            ps0 += s[nt][0] + s[nt][1];
            ps1 += s[nt][2] + s[nt][3];
        }
        ps0 += __shfl_xor_sync(0xffffffffu, ps0, 1);
        ps0 += __shfl_xor_sync(0xffffffffu, ps0, 2);
        ps1 += __shfl_xor_sync(0xffffffffu, ps1, 1);
        ps1 += __shfl_xor_sync(0xffffffffu, ps1, 2);
        l0 = l0 * sc0 + ps0;
        l1 = l1 * sc1 + ps1;

        #pragma unroll
        for (int nt = 0; nt < 8; nt++) {
            o[nt][0] *= sc0; o[nt][1] *= sc0;
            o[nt][2] *= sc1; o[nt][3] *= sc1;
        }

        // P (fp16) -> warp-private smem; reload as A fragments
        #pragma unroll
        for (int nt = 0; nt < 8; nt++) {
            const int pc = nt * 8 + 2 * c4;
            *(unsigned*)&sp[warp][r4    ][pc] = h2u(__floats2half2_rn(s[nt][0], s[nt][1]));
            *(unsigned*)&sp[warp][r4 + 8][pc] = h2u(__floats2half2_rn(s[nt][2], s[nt][3]));
        }
        __syncwarp();

        unsigned pa[4][4];
        #pragma unroll
        for (int ks = 0; ks < 4; ks++) {
            const int kk = ks * 16 + 2 * c4;
            pa[ks][0] = *(const unsigned*)&sp[warp][r4    ][kk    ];
            pa[ks][1] = *(const unsigned*)&sp[warp][r4 + 8][kk    ];
            pa[ks][2] = *(const unsigned*)&sp[warp][r4    ][kk + 8];
            pa[ks][3] = *(const unsigned*)&sp[warp][r4 + 8][kk + 8];
        }

        // O += P @ V : 8 dh n-tiles x 4 k16 steps
        #pragma unroll
        for (int nt = 0; nt < 8; nt++) {
            #pragma unroll
            for (int ks = 0; ks < 4; ks++) {
                unsigned bf[2];
                bf[0] = sv2[ks * 8 + c4    ][nt * 8 + r4];
                bf[1] = sv2[ks * 8 + c4 + 4][nt * 8 + r4];
                mma_f16(o[nt], pa[ks], bf);
            }
        }
        __syncwarp();
    }

    // epilogue: normalize and store
    const float inv0 = 1.0f / l0;
    const float inv1 = 1.0f / l1;
    const int rA = qrow0 + r4;
    const int rB = rA + 8;
    float* oA = out + ((size_t)(b * SS + rA)) * DD + h * DH;
    float* oB = out + ((size_t)(b * SS + rB)) * DD + h * DH;
    #pragma unroll
    for (int nt = 0; nt < 8; nt++) {
        const int d = nt * 8 + 2 * c4;
        *(float2*)(oA + d) = make_float2(o[nt][0] * inv0, o[nt][1] * inv0);
        *(float2*)(oB + d) = make_float2(o[nt][2] * inv1, o[nt][3] * inv1);
    }
}

extern "C" void kernel_launch(void* const* d_in, const int* in_sizes, int n_in,
                              void* d_out, int out_size)
{
    const float* x  = (const float*)d_in[0];
    const float* Wq = (const float*)d_in[1];
    const float* bq = (const float*)d_in[2];
    const float* Wk = (const float*)d_in[3];
    const float* bk = (const float*)d_in[4];
    const float* Wv = (const float*)d_in[5];
    const float* bv = (const float*)d_in[6];
    float* out = (float*)d_out;

    __half* gxh; cudaGetSymbolAddress((void**)&gxh, g_xh);
    __half* gwh; cudaGetSymbolAddress((void**)&gwh, g_wh);

    to_half<<<(BB * SS * DD / 8 + 255) / 256, 256>>>(gxh, x, BB * SS * DD / 8);
    to_half<<<(DD * DD / 8 + 255) / 256, 256>>>(gwh,               Wq, DD * DD / 8);
    to_half<<<(DD * DD / 8 + 255) / 256, 256>>>(gwh + DD * DD,     Wk, DD * DD / 8);
    to_half<<<(DD * DD / 8 + 255) / 256, 256>>>(gwh + 2 * DD * DD, Wv, DD * DD / 8);

    dim3 gg(DD / 128, (BB * SS) / 128);   // (8, 128)
    qkv_gemm<<<gg, 256>>>(bq, 0);
    qkv_gemm<<<gg, 256>>>(bk, 1);
    qkv_gemm<<<gg, 256>>>(bv, 2);

    dim3 ga(SS / 64, BB * HH);            // (16, 256)
    attn_kernel<<<ga, 128>>>(out);
}

// round 16
// speedup vs baseline: 1.0111x; 1.0111x over previous
#include <cuda_runtime.h>
#include <cuda_fp16.h>
#include <math.h>

#define BB 16
#define SS 1024
#define DD 1024
#define HH 16
#define DH 64

// Device scratch (no allocations allowed). All-fp16 pipeline:
__device__ __half g_qh[BB * HH * SS * DH];  // Q * 0.125, fp16, head-split
__device__ __half g_kh[BB * HH * SS * DH];  // K fp16
__device__ __half g_vh[BB * HH * SS * DH];  // V fp16
__device__ __half g_xh[BB * SS * DD];       // fp16 X
__device__ __half g_wh[3 * DD * DD];        // fp16 Wq,Wk,Wv

// ---------------------------------------------------------------------------
__device__ __forceinline__ void mma_f16(float* d, const unsigned* a, const unsigned* b) {
    asm volatile(
        "mma.sync.aligned.m16n8k16.row.col.f32.f16.f16.f32 "
        "{%0,%1,%2,%3},{%4,%5,%6,%7},{%8,%9},{%0,%1,%2,%3};"
        : "+f"(d[0]), "+f"(d[1]), "+f"(d[2]), "+f"(d[3])
        : "r"(a[0]), "r"(a[1]), "r"(a[2]), "r"(a[3]), "r"(b[0]), "r"(b[1]));
}

__device__ __forceinline__ unsigned h2u(__half2 h) {
    return *(unsigned*)&h;
}

// ---------------------------------------------------------------------------
// Pre-pass: fp32 -> fp16 (rn), 8 elements per thread.
// ---------------------------------------------------------------------------
__global__ void to_half(__half* __restrict__ dst, const float* __restrict__ src, int n8)
{
    int i = blockIdx.x * blockDim.x + threadIdx.x;
    if (i < n8) {
        float4 a = ((const float4*)src)[2 * i];
        float4 b = ((const float4*)src)[2 * i + 1];
        uint4 u;
        u.x = h2u(__floats2half2_rn(a.x, a.y));
        u.y = h2u(__floats2half2_rn(a.z, a.w));
        u.z = h2u(__floats2half2_rn(b.x, b.y));
        u.w = h2u(__floats2half2_rn(b.z, b.w));
        ((uint4*)dst)[i] = u;
    }
}

// ---------------------------------------------------------------------------
// QKV projection: Yh = fp16((X @ W^T + b) * scale), head-split store.
// R11/R13-proven loop cadence; fp16 source and fp16 output.
// BM=BN=128, BK=32, 256 thr (8 warps 4x2), warp tile 32x64.
// ---------------------------------------------------------------------------
__global__ __launch_bounds__(256)
void qkv_gemm(const float* __restrict__ bias, int which)
{
    __shared__ __half sa[128][40];   // [m][k]
    __shared__ __half sb[128][40];   // [n][k]

    __half* __restrict__ Yh = (which == 0) ? g_qh : (which == 1) ? g_kh : g_vh;
    const __half* __restrict__ Xh = g_xh;
    const __half* __restrict__ Wh = g_wh + (size_t)which * DD * DD;
    const float scale = (which == 0) ? 0.125f : 1.0f;

    const int tid  = threadIdx.x;
    const int lane = tid & 31;
    const int warp = tid >> 5;
    const int wm   = (warp & 3) * 32;
    const int wn   = (warp >> 2) * 64;
    const int m0   = blockIdx.y * 128;
    const int n0   = blockIdx.x * 128;

    const int lr = tid >> 3;        // 0..31
    const int lc = (tid & 7) * 4;   // half cols 0,4,...,28

    const int r4 = lane >> 2;
    const int c4 = lane & 3;

    float acc[2][8][4];
    #pragma unroll
    for (int i = 0; i < 2; i++)
        #pragma unroll
        for (int j = 0; j < 8; j++)
            #pragma unroll
            for (int c = 0; c < 4; c++) acc[i][j][c] = 0.0f;

    for (int k0 = 0; k0 < DD; k0 += 32) {
        uint2 ua[4], ub[4];
        #pragma unroll
        for (int i = 0; i < 4; i++) {
            ua[i] = *(const uint2*)(Xh + (size_t)(m0 + lr + 32 * i) * DD + k0 + lc);
            ub[i] = *(const uint2*)(Wh + (size_t)(n0 + lr + 32 * i) * DD + k0 + lc);
        }
        __syncthreads();
        #pragma unroll
        for (int i = 0; i < 4; i++) {
            *(uint2*)&sa[lr + 32 * i][lc] = ua[i];
            *(uint2*)&sb[lr + 32 * i][lc] = ub[i];
        }
        __syncthreads();

        #pragma unroll
        for (int ks = 0; ks < 2; ks++) {
            const int kk = ks * 16 + 2 * c4;
            unsigned af[2][4];
            #pragma unroll
            for (int mt = 0; mt < 2; mt++) {
                const int rb = wm + mt * 16;
                af[mt][0] = *(const unsigned*)&sa[rb + r4    ][kk    ];
                af[mt][1] = *(const unsigned*)&sa[rb + r4 + 8][kk    ];
                af[mt][2] = *(const unsigned*)&sa[rb + r4    ][kk + 8];
                af[mt][3] = *(const unsigned*)&sa[rb + r4 + 8][kk + 8];
            }
            #pragma unroll
            for (int nt = 0; nt < 8; nt++) {
                const int cb = wn + nt * 8;
                unsigned bf[2];
                bf[0] = *(const unsigned*)&sb[cb + r4][kk    ];
                bf[1] = *(const unsigned*)&sb[cb + r4][kk + 8];
                mma_f16(acc[0][nt], af[0], bf);
                mma_f16(acc[1][nt], af[1], bf);
            }
        }
    }

    // Epilogue: fp16((acc + bias) * scale), head-split scatter.
    #pragma unroll
    for (int mt = 0; mt < 2; mt++) {
        const int mA = m0 + wm + mt * 16 + r4;
        const int mB = mA + 8;
        const int bA = mA >> 10, sA_ = mA & 1023;
        const int bB = mB >> 10, sB_ = mB & 1023;
        #pragma unroll
        for (int nt = 0; nt < 8; nt++) {
            const int col = n0 + wn + nt * 8 + 2 * c4;
            const int h = col >> 6, d = col & 63;
            const float b0 = bias[col], b1 = bias[col + 1];
            unsigned vA = h2u(__floats2half2_rn((acc[mt][nt][0] + b0) * scale,
                                                (acc[mt][nt][1] + b1) * scale));
            unsigned vB = h2u(__floats2half2_rn((acc[mt][nt][2] + b0) * scale,
                                                (acc[mt][nt][3] + b1) * scale));
            *(unsigned*)(Yh + (((size_t)(bA * HH + h) * SS + sA_) * DH) + d) = vA;
            *(unsigned*)(Yh + (((size_t)(bB * HH + h) * SS + sB_) * DH) + d) = vB;
        }
    }
}

// ---------------------------------------------------------------------------
// Flash attention, fp16 mma, BC=64. fp16 Q/K/V inputs: Q/K staging = pure
// copy; V staging = fully-coalesced fp16 loads (8 lanes cover one 128B row)
// + byte_perm pair-interleave. Block = 128 thr (4 warps), 16 q-rows/warp.
// ---------------------------------------------------------------------------
__global__ __launch_bounds__(128)
void attn_kernel(float* __restrict__ out)
{
    __shared__ __half sk[64][72];
    __shared__ unsigned sv2[32][72];
    __shared__ __half sp[4][16][72];

    const int tid  = threadIdx.x;
    const int lane = tid & 31;
    const int warp = tid >> 5;
    const int bh   = blockIdx.y;
    const int b    = bh >> 4;
    const int h    = bh & 15;
    const int qrow0 = blockIdx.x * 64 + warp * 16;

    const int r4 = lane >> 2;
    const int c4 = lane & 3;

    const __half* Qh = g_qh + (size_t)bh * SS * DH;
    const __half* Kh = g_kh + (size_t)bh * SS * DH;
    const __half* Vh = g_vh + (size_t)bh * SS * DH;

    // stage Q (already scaled, fp16): pure copy into sp[warp]
    {
        #pragma unroll
        for (int i = 0; i < 4; i++) {
            const int idx = lane + i * 32;          // 0..127
            const int row = idx >> 3;               // 0..15
            const int cc  = (idx & 7) * 8;
            uint4 t = *(const uint4*)(Qh + (size_t)(qrow0 + row) * DH + cc);
            *(uint4*)&sp[warp][row][cc] = t;
        }
    }
    __syncwarp();
    unsigned qa[4][4];
    #pragma unroll
    for (int ks = 0; ks < 4; ks++) {
        const int kk = ks * 16 + 2 * c4;
        qa[ks][0] = *(const unsigned*)&sp[warp][r4    ][kk    ];
        qa[ks][1] = *(const unsigned*)&sp[warp][r4 + 8][kk    ];
        qa[ks][2] = *(const unsigned*)&sp[warp][r4    ][kk + 8];
        qa[ks][3] = *(const unsigned*)&sp[warp][r4 + 8][kk + 8];
    }
    __syncwarp();

    float o[8][4];
    #pragma unroll
    for (int nt = 0; nt < 8; nt++)
        #pragma unroll
        for (int c = 0; c < 4; c++) o[nt][c] = 0.0f;
    float m0v = -INFINITY, m1v = -INFINITY;
    float l0 = 0.0f, l1 = 0.0f;

    for (int t0 = 0; t0 < SS; t0 += 64) {
        __syncthreads();
        // K: 64 rows x 64 halfs: pure copy, 4 x uint4 per thread
        #pragma unroll
        for (int i = 0; i < 4; i++) {
            const int idx = tid + i * 128;          // 0..511
            const int row = idx >> 3;               // 0..63
            const int cc  = (idx & 7) * 8;
            uint4 t = *(const uint4*)(Kh + (size_t)(t0 + row) * DH + cc);
            *(uint4*)&sk[row][cc] = t;
        }
        // V: coalesced: 8 lanes x 16B = one full 128B row per instruction.
        // thread -> kv pair kvp, d-range [d0, d0+8); loads that 16B range from
        // both rows of the pair and interleaves.
        #pragma unroll
        for (int i = 0; i < 2; i++) {
            const int kvp = (tid >> 3) + i * 16;    // 0..31
            const int d0  = (tid & 7) * 8;          // 0,8,...,56
            const __half* v0 = Vh + (size_t)(t0 + 2 * kvp) * DH + d0;
            const __half* v1 = v0 + DH;
            uint4 A = *(const uint4*)(v0);
            uint4 B = *(const uint4*)(v1);
            uint4 w;
            w.x = __byte_perm(A.x, B.x, 0x5410);
            w.y = __byte_perm(A.x, B.x, 0x7632);
            w.z = __byte_perm(A.y, B.y, 0x5410);
            w.w = __byte_perm(A.y, B.y, 0x7632);
            *(uint4*)&sv2[kvp][d0] = w;
            w.x = __byte_perm(A.z, B.z, 0x5410);
            w.y = __byte_perm(A.z, B.z, 0x7632);
            w.z = __byte_perm(A.w, B.w, 0x5410);
            w.w = __byte_perm(A.w, B.w, 0x7632);
            *(uint4*)&sv2[kvp][d0 + 4] = w;
        }
        __syncthreads();

        // S = Q @ K^T : 8 kv n-tiles x 4 k16 steps
        float s[8][4];
        #pragma unroll
        for (int nt = 0; nt < 8; nt++) {
            #pragma unroll
            for (int c = 0; c < 4; c++) s[nt][c] = 0.0f;
            #pragma unroll
            for (int ks = 0; ks < 4; ks++) {
                const int kk = ks * 16 + 2 * c4;
                unsigned bf[2];
                bf[0] = *(const unsigned*)&sk[nt * 8 + r4][kk    ];
                bf[1] = *(const unsigned*)&sk[nt * 8 + r4][kk + 8];
                mma_f16(s[nt], qa[ks], bf);
            }
        }

        // online softmax (fp32)
        float tm0 = -INFINITY, tm1 = -INFINITY;
        #pragma unroll
        for (int nt = 0; nt < 8; nt++) {
            tm0 = fmaxf(tm0, fmaxf(s[nt][0], s[nt][1]));
            tm1 = fmaxf(tm1, fmaxf(s[nt][2], s[nt][3]));
        }
        tm0 = fmaxf(tm0, __shfl_xor_sync(0xffffffffu, tm0, 1));
        tm0 = fmaxf(tm0, __shfl_xor_sync(0xffffffffu, tm0, 2));
        tm1 = fmaxf(tm1, __shfl_xor_sync(0xffffffffu, tm1, 1));
        tm1 = fmaxf(tm1, __shfl_xor_sync(0xffffffffu, tm1, 2));

        const float mn0 = fmaxf(m0v, tm0);
        const float mn1 = fmaxf(m1v, tm1);
        const float sc0 = __expf(m0v - mn0);
        const float sc1 = __expf(m1v - mn1);
        m0v = mn0; m1v = mn1;

        float ps0 = 0.0f, ps1 = 0.0f;
        #pragma unroll
        for (int nt = 0; nt < 8; nt++) {
            s[nt][0] = __expf(s[nt][0] - mn0);
            s[nt][1] = __expf(s[nt][1] - mn0);
            s[nt][2] = __expf(s[nt][2] - mn1);
            s[nt][3] = __expf(s[nt][3] - mn1);
            ps0 += s[nt][0] + s[nt][1];
            ps1 += s[nt][2] + s[nt][3];
        }
        ps0 += __shfl_xor_sync(0xffffffffu, ps0, 1);
        ps0 += __shfl_xor_sync(0xffffffffu, ps0, 2);
        ps1 += __shfl_xor_sync(0xffffffffu, ps1, 1);
        ps1 += __shfl_xor_sync(0xffffffffu, ps1, 2);
        l0 = l0 * sc0 + ps0;
        l1 = l1 * sc1 + ps1;

        #pragma unroll
        for (int nt = 0; nt < 8; nt++) {
            o[nt][0] *= sc0; o[nt][1] *= sc0;
            o[nt][2] *= sc1; o[nt][3] *= sc1;
        }

        // P (fp16) -> warp-private smem; reload as A fragments
        #pragma unroll
        for (int nt = 0; nt < 8; nt++) {
            const int pc = nt * 8 + 2 * c4;
            *(unsigned*)&sp[warp][r4    ][pc] = h2u(__floats2half2_rn(s[nt][0], s[nt][1]));
            *(unsigned*)&sp[warp][r4 + 8][pc] = h2u(__floats2half2_rn(s[nt][2], s[nt][3]));
        }
        __syncwarp();

        unsigned pa[4][4];
        #pragma unroll
        for (int ks = 0; ks < 4; ks++) {
            const int kk = ks * 16 + 2 * c4;
            pa[ks][0] = *(const unsigned*)&sp[warp][r4    ][kk    ];
            pa[ks][1] = *(const unsigned*)&sp[warp][r4 + 8][kk    ];
            pa[ks][2] = *(const unsigned*)&sp[warp][r4    ][kk + 8];
            pa[ks][3] = *(const unsigned*)&sp[warp][r4 + 8][kk + 8];
        }

        // O += P @ V : 8 dh n-tiles x 4 k16 steps
        #pragma unroll
        for (int nt = 0; nt < 8; nt++) {
            #pragma unroll
            for (int ks = 0; ks < 4; ks++) {
                unsigned bf[2];
                bf[0] = sv2[ks * 8 + c4    ][nt * 8 + r4];
                bf[1] = sv2[ks * 8 + c4 + 4][nt * 8 + r4];
                mma_f16(o[nt], pa[ks], bf);
            }
        }
        __syncwarp();
    }

    // epilogue: normalize and store
    const float inv0 = 1.0f / l0;
    const float inv1 = 1.0f / l1;
    const int rA = qrow0 + r4;
    const int rB = rA + 8;
    float* oA = out + ((size_t)(b * SS + rA)) * DD + h * DH;
    float* oB = out + ((size_t)(b * SS + rB)) * DD + h * DH;
    #pragma unroll
    for (int nt = 0; nt < 8; nt++) {
        const int d = nt * 8 + 2 * c4;
        *(float2*)(oA + d) = make_float2(o[nt][0] * inv0, o[nt][1] * inv0);
        *(float2*)(oB + d) = make_float2(o[nt][2] * inv1, o[nt][3] * inv1);
    }
}

extern "C" void kernel_launch(void* const* d_in, const int* in_sizes, int n_in,
                              void* d_out, int out_size)
{
    const float* x  = (const float*)d_in[0];
    const float* Wq = (const float*)d_in[1];
    const float* bq = (const float*)d_in[2];
    const float* Wk = (const float*)d_in[3];
    const float* bk = (const float*)d_in[4];
    const float* Wv = (const float*)d_in[5];
    const float* bv = (const float*)d_in[6];
    float* out = (float*)d_out;

    __half* gxh; cudaGetSymbolAddress((void**)&gxh, g_xh);
    __half* gwh; cudaGetSymbolAddress((void**)&gwh, g_wh);

    to_half<<<(BB * SS * DD / 8 + 255) / 256, 256>>>(gxh, x, BB * SS * DD / 8);
    to_half<<<(DD * DD / 8 + 255) / 256, 256>>>(gwh,               Wq, DD * DD / 8);
    to_half<<<(DD * DD / 8 + 255) / 256, 256>>>(gwh + DD * DD,     Wk, DD * DD / 8);
    to_half<<<(DD * DD / 8 + 255) / 256, 256>>>(gwh + 2 * DD * DD, Wv, DD * DD / 8);

    dim3 gg(DD / 128, (BB * SS) / 128);   // (8, 128)
    qkv_gemm<<<gg, 256>>>(bq, 0);
    qkv_gemm<<<gg, 256>>>(bk, 1);
    qkv_gemm<<<gg, 256>>>(bv, 2);

    dim3 ga(SS / 64, BB * HH);            // (16, 256)
    attn_kernel<<<ga, 128>>>(out);
}

// round 17
// speedup vs baseline: 1.5850x; 1.5676x over previous
#include <cuda_runtime.h>
#include <cuda_fp16.h>
#include <math.h>

#define BB 16
#define SS 1024
#define DD 1024
#define HH 16
#define DH 64

// Device scratch (no allocations allowed). All-fp16 pipeline:
__device__ __half g_qh[BB * HH * SS * DH];  // Q * 0.125, fp16, head-split
__device__ __half g_kh[BB * HH * SS * DH];  // K fp16
__device__ __half g_vh[BB * HH * SS * DH];  // V fp16
__device__ __half g_xh[BB * SS * DD];       // fp16 X
__device__ __half g_wh[3 * DD * DD];        // fp16 Wq,Wk,Wv

// ---------------------------------------------------------------------------
__device__ __forceinline__ void mma_f16(float* d, const unsigned* a, const unsigned* b) {
    asm volatile(
        "mma.sync.aligned.m16n8k16.row.col.f32.f16.f16.f32 "
        "{%0,%1,%2,%3},{%4,%5,%6,%7},{%8,%9},{%0,%1,%2,%3};"
        : "+f"(d[0]), "+f"(d[1]), "+f"(d[2]), "+f"(d[3])
        : "r"(a[0]), "r"(a[1]), "r"(a[2]), "r"(a[3]), "r"(b[0]), "r"(b[1]));
}

__device__ __forceinline__ void ldsm_x4(unsigned* d, unsigned addr) {
    asm volatile("ldmatrix.sync.aligned.m8n8.x4.shared.b16 {%0,%1,%2,%3}, [%4];"
        : "=r"(d[0]), "=r"(d[1]), "=r"(d[2]), "=r"(d[3]) : "r"(addr));
}

__device__ __forceinline__ unsigned h2u(__half2 h) {
    return *(unsigned*)&h;
}

__device__ __forceinline__ unsigned smem_addr(const void* p) {
    return (unsigned)__cvta_generic_to_shared(p);
}

// ---------------------------------------------------------------------------
// Pre-pass: fp32 -> fp16 (rn), 8 elements per thread.
// ---------------------------------------------------------------------------
__global__ void to_half(__half* __restrict__ dst, const float* __restrict__ src, int n8)
{
    int i = blockIdx.x * blockDim.x + threadIdx.x;
    if (i < n8) {
        float4 a = ((const float4*)src)[2 * i];
        float4 b = ((const float4*)src)[2 * i + 1];
        uint4 u;
        u.x = h2u(__floats2half2_rn(a.x, a.y));
        u.y = h2u(__floats2half2_rn(a.z, a.w));
        u.z = h2u(__floats2half2_rn(b.x, b.y));
        u.w = h2u(__floats2half2_rn(b.z, b.w));
        ((uint4*)dst)[i] = u;
    }
}

// ---------------------------------------------------------------------------
// QKV projection: Yh = fp16((X @ W^T + b) * scale), head-split store.
// R11/R13 loop cadence; fragment loads via ldmatrix.x4 (4x fewer shared ops).
// BM=BN=128, BK=32, 256 thr (8 warps 4x2), warp tile 32x64, stride-40 smem.
// ---------------------------------------------------------------------------
__global__ __launch_bounds__(256)
void qkv_gemm(const float* __restrict__ bias, int which)
{
    __shared__ __half sa[128][40];   // [m][k]
    __shared__ __half sb[128][40];   // [n][k]

    __half* __restrict__ Yh = (which == 0) ? g_qh : (which == 1) ? g_kh : g_vh;
    const __half* __restrict__ Xh = g_xh;
    const __half* __restrict__ Wh = g_wh + (size_t)which * DD * DD;
    const float scale = (which == 0) ? 0.125f : 1.0f;

    const int tid  = threadIdx.x;
    const int lane = tid & 31;
    const int warp = tid >> 5;
    const int wm   = (warp & 3) * 32;
    const int wn   = (warp >> 2) * 64;
    const int m0   = blockIdx.y * 128;
    const int n0   = blockIdx.x * 128;

    const int lr = tid >> 3;        // 0..31
    const int lc = (tid & 7) * 4;   // half cols 0,4,...,28

    const int r4 = lane >> 2;
    const int c4 = lane & 3;

    // ldmatrix per-lane bases:
    // A-type: groups (row+0,k+0)(row+8,k+0)(row+0,k+8)(row+8,k+8)
    const int aRow = (lane & 7) + ((lane >> 3) & 1) * 8;
    const int aK   = (lane >> 4) * 8;
    // B-type: groups (n+0,k+0)(n+0,k+8)(n+8,k+0)(n+8,k+8)
    const int bRow = (lane & 7) + ((lane >> 4) & 1) * 8;
    const int bK   = ((lane >> 3) & 1) * 8;
    const unsigned aBase = smem_addr(&sa[aRow][aK]);
    const unsigned bBase = smem_addr(&sb[bRow][bK]);

    float acc[2][8][4];
    #pragma unroll
    for (int i = 0; i < 2; i++)
        #pragma unroll
        for (int j = 0; j < 8; j++)
            #pragma unroll
            for (int c = 0; c < 4; c++) acc[i][j][c] = 0.0f;

    for (int k0 = 0; k0 < DD; k0 += 32) {
        uint2 ua[4], ub[4];
        #pragma unroll
        for (int i = 0; i < 4; i++) {
            ua[i] = *(const uint2*)(Xh + (size_t)(m0 + lr + 32 * i) * DD + k0 + lc);
            ub[i] = *(const uint2*)(Wh + (size_t)(n0 + lr + 32 * i) * DD + k0 + lc);
        }
        __syncthreads();
        #pragma unroll
        for (int i = 0; i < 4; i++) {
            *(uint2*)&sa[lr + 32 * i][lc] = ua[i];
            *(uint2*)&sb[lr + 32 * i][lc] = ub[i];
        }
        __syncthreads();

        #pragma unroll
        for (int ks = 0; ks < 2; ks++) {
            const unsigned koff = ks * 32;            // (ks*16 halfs)*2 bytes
            unsigned af[2][4];
            ldsm_x4(af[0], aBase + (unsigned)(wm * 80) + koff);
            ldsm_x4(af[1], aBase + (unsigned)((wm + 16) * 80) + koff);
            unsigned bf[8][2];
            #pragma unroll
            for (int j = 0; j < 4; j++) {
                unsigned d[4];
                ldsm_x4(d, bBase + (unsigned)((wn + j * 16) * 80) + koff);
                bf[2*j  ][0] = d[0]; bf[2*j  ][1] = d[1];
                bf[2*j+1][0] = d[2]; bf[2*j+1][1] = d[3];
            }
            #pragma unroll
            for (int nt = 0; nt < 8; nt++) {
                mma_f16(acc[0][nt], af[0], bf[nt]);
                mma_f16(acc[1][nt], af[1], bf[nt]);
            }
        }
    }

    // Epilogue: fp16((acc + bias) * scale), head-split scatter.
    #pragma unroll
    for (int mt = 0; mt < 2; mt++) {
        const int mA = m0 + wm + mt * 16 + r4;
        const int mB = mA + 8;
        const int bA = mA >> 10, sA_ = mA & 1023;
        const int bB = mB >> 10, sB_ = mB & 1023;
        #pragma unroll
        for (int nt = 0; nt < 8; nt++) {
            const int col = n0 + wn + nt * 8 + 2 * c4;
            const int h = col >> 6, d = col & 63;
            const float b0 = bias[col], b1 = bias[col + 1];
            unsigned vA = h2u(__floats2half2_rn((acc[mt][nt][0] + b0) * scale,
                                                (acc[mt][nt][1] + b1) * scale));
            unsigned vB = h2u(__floats2half2_rn((acc[mt][nt][2] + b0) * scale,
                                                (acc[mt][nt][3] + b1) * scale));
            *(unsigned*)(Yh + (((size_t)(bA * HH + h) * SS + sA_) * DH) + d) = vA;
            *(unsigned*)(Yh + (((size_t)(bB * HH + h) * SS + sB_) * DH) + d) = vB;
        }
    }
}

// ---------------------------------------------------------------------------
// Flash attention, fp16 mma, BC=64. K and Q/P fragments via ldmatrix.x4;
// V via verified-conflict-free scalar LDS. Block = 128 thr, 16 q-rows/warp.
// ---------------------------------------------------------------------------
__global__ __launch_bounds__(128)
void attn_kernel(float* __restrict__ out)
{
    __shared__ __half sk[64][72];
    __shared__ unsigned sv2[32][72];
    __shared__ __half sp[4][16][72];

    const int tid  = threadIdx.x;
    const int lane = tid & 31;
    const int warp = tid >> 5;
    const int bh   = blockIdx.y;
    const int b    = bh >> 4;
    const int h    = bh & 15;
    const int qrow0 = blockIdx.x * 64 + warp * 16;

    const int r4 = lane >> 2;
    const int c4 = lane & 3;

    const __half* Qh = g_qh + (size_t)bh * SS * DH;
    const __half* Kh = g_kh + (size_t)bh * SS * DH;
    const __half* Vh = g_vh + (size_t)bh * SS * DH;

    // ldmatrix per-lane bases (stride 72 halfs = 144 B)
    const int aRow = (lane & 7) + ((lane >> 3) & 1) * 8;
    const int aK   = (lane >> 4) * 8;
    const int bRow = (lane & 7) + ((lane >> 4) & 1) * 8;
    const int bK   = ((lane >> 3) & 1) * 8;
    const unsigned spBase = smem_addr(&sp[warp][aRow][aK]);
    const unsigned kBase  = smem_addr(&sk[bRow][bK]);

    // stage Q (already scaled, fp16): pure copy into sp[warp]
    {
        #pragma unroll
        for (int i = 0; i < 4; i++) {
            const int idx = lane + i * 32;          // 0..127
            const int row = idx >> 3;               // 0..15
            const int cc  = (idx & 7) * 8;
            uint4 t = *(const uint4*)(Qh + (size_t)(qrow0 + row) * DH + cc);
            *(uint4*)&sp[warp][row][cc] = t;
        }
    }
    __syncwarp();
    unsigned qa[4][4];
    #pragma unroll
    for (int ks = 0; ks < 4; ks++)
        ldsm_x4(qa[ks], spBase + (unsigned)(ks * 32));
    __syncwarp();

    float o[8][4];
    #pragma unroll
    for (int nt = 0; nt < 8; nt++)
        #pragma unroll
        for (int c = 0; c < 4; c++) o[nt][c] = 0.0f;
    float m0v = -INFINITY, m1v = -INFINITY;
    float l0 = 0.0f, l1 = 0.0f;

    for (int t0 = 0; t0 < SS; t0 += 64) {
        __syncthreads();
        // K: 64 rows x 64 halfs: pure copy, 4 x uint4 per thread
        #pragma unroll
        for (int i = 0; i < 4; i++) {
            const int idx = tid + i * 128;          // 0..511
            const int row = idx >> 3;               // 0..63
            const int cc  = (idx & 7) * 8;
            uint4 t = *(const uint4*)(Kh + (size_t)(t0 + row) * DH + cc);
            *(uint4*)&sk[row][cc] = t;
        }
        // V: coalesced fp16 loads (8 lanes cover one 128B row) + byte_perm
        #pragma unroll
        for (int i = 0; i < 2; i++) {
            const int kvp = (tid >> 3) + i * 16;    // 0..31
            const int d0  = (tid & 7) * 8;          // 0,8,...,56
            const __half* v0 = Vh + (size_t)(t0 + 2 * kvp) * DH + d0;
            const __half* v1 = v0 + DH;
            uint4 A = *(const uint4*)(v0);
            uint4 B = *(const uint4*)(v1);
            uint4 w;
            w.x = __byte_perm(A.x, B.x, 0x5410);
            w.y = __byte_perm(A.x, B.x, 0x7632);
            w.z = __byte_perm(A.y, B.y, 0x5410);
            w.w = __byte_perm(A.y, B.y, 0x7632);
            *(uint4*)&sv2[kvp][d0] = w;
            w.x = __byte_perm(A.z, B.z, 0x5410);
            w.y = __byte_perm(A.z, B.z, 0x7632);
            w.z = __byte_perm(A.w, B.w, 0x5410);
            w.w = __byte_perm(A.w, B.w, 0x7632);
            *(uint4*)&sv2[kvp][d0 + 4] = w;
        }
        __syncthreads();

        // S = Q @ K^T : per ks load 8 nt K-frags with 4 ldmatrix.x4
        float s[8][4];
        #pragma unroll
        for (int nt = 0; nt < 8; nt++)
            #pragma unroll
            for (int c = 0; c < 4; c++) s[nt][c] = 0.0f;
        #pragma unroll
        for (int ks = 0; ks < 4; ks++) {
            const unsigned koff = ks * 32;
            unsigned bf[8][2];
            #pragma unroll
            for (int j = 0; j < 4; j++) {
                unsigned d[4];
                ldsm_x4(d, kBase + (unsigned)(j * 16 * 144) + koff);
                bf[2*j  ][0] = d[0]; bf[2*j  ][1] = d[1];
                bf[2*j+1][0] = d[2]; bf[2*j+1][1] = d[3];
            }
            #pragma unroll
            for (int nt = 0; nt < 8; nt++)
                mma_f16(s[nt], qa[ks], bf[nt]);
        }

        // online softmax (fp32)
        float tm0 = -INFINITY, tm1 = -INFINITY;
        #pragma unroll
        for (int nt = 0; nt < 8; nt++) {
            tm0 = fmaxf(tm0, fmaxf(s[nt][0], s[nt][1]));
            tm1 = fmaxf(tm1, fmaxf(s[nt][2], s[nt][3]));
        }
        tm0 = fmaxf(tm0, __shfl_xor_sync(0xffffffffu, tm0, 1));
        tm0 = fmaxf(tm0, __shfl_xor_sync(0xffffffffu, tm0, 2));
        tm1 = fmaxf(tm1, __shfl_xor_sync(0xffffffffu, tm1, 1));
        tm1 = fmaxf(tm1, __shfl_xor_sync(0xffffffffu, tm1, 2));

        const float mn0 = fmaxf(m0v, tm0);
        const float mn1 = fmaxf(m1v, tm1);
        const float sc0 = __expf(m0v - mn0);
        const float sc1 = __expf(m1v - mn1);
        m0v = mn0; m1v = mn1;

        float ps0 = 0.0f, ps1 = 0.0f;
        #pragma unroll
        for (int nt = 0; nt < 8; nt++) {
            s[nt][0] = __expf(s[nt][0] - mn0);
            s[nt][1] = __expf(s[nt][1] - mn0);
            s[nt][2] = __expf(s[nt][2] - mn1);
            s[nt][3] = __expf(s[nt][3] - mn1);
            ps0 += s[nt][0] + s[nt][1];
            ps1 += s[nt][2] + s[nt][3];
        }
        ps0 += __shfl_xor_sync(0xffffffffu, ps0, 1);
        ps0 += __shfl_xor_sync(0xffffffffu, ps0, 2);
        ps1 += __shfl_xor_sync(0xffffffffu, ps1, 1);
        ps1 += __shfl_xor_sync(0xffffffffu, ps1, 2);
        l0 = l0 * sc0 + ps0;
        l1 = l1 * sc1 + ps1;

        #pragma unroll
        for (int nt = 0; nt < 8; nt++) {
            o[nt][0] *= sc0; o[nt][1] *= sc0;
            o[nt][2] *= sc1; o[nt][3] *= sc1;
        }

        // P (fp16) -> warp-private smem; reload as A fragments via ldmatrix
        #pragma unroll
        for (int nt = 0; nt < 8; nt++) {
            const int pc = nt * 8 + 2 * c4;
            *(unsigned*)&sp[warp][r4    ][pc] = h2u(__floats2half2_rn(s[nt][0], s[nt][1]));
            *(unsigned*)&sp[warp][r4 + 8][pc] = h2u(__floats2half2_rn(s[nt][2], s[nt][3]));
        }
        __syncwarp();

        unsigned pa[4][4];
        #pragma unroll
        for (int ks = 0; ks < 4; ks++)
            ldsm_x4(pa[ks], spBase + (unsigned)(ks * 32));

        // O += P @ V : 8 dh n-tiles x 4 k16 steps (V scalar LDS, conflict-free)
        #pragma unroll
        for (int nt = 0; nt < 8; nt++) {
            #pragma unroll
            for (int ks = 0; ks < 4; ks++) {
                unsigned bf[2];
                bf[0] = sv2[ks * 8 + c4    ][nt * 8 + r4];
                bf[1] = sv2[ks * 8 + c4 + 4][nt * 8 + r4];
                mma_f16(o[nt], pa[ks], bf);
            }
        }
        __syncwarp();
    }

    // epilogue: normalize and store
    const float inv0 = 1.0f / l0;
    const float inv1 = 1.0f / l1;
    const int rA = qrow0 + r4;
    const int rB = rA + 8;
    float* oA = out + ((size_t)(b * SS + rA)) * DD + h * DH;
    float* oB = out + ((size_t)(b * SS + rB)) * DD + h * DH;
    #pragma unroll
    for (int nt = 0; nt < 8; nt++) {
        const int d = nt * 8 + 2 * c4;
        *(float2*)(oA + d) = make_float2(o[nt][0] * inv0, o[nt][1] * inv0);
        *(float2*)(oB + d) = make_float2(o[nt][2] * inv1, o[nt][3] * inv1);
    }
}

extern "C" void kernel_launch(void* const* d_in, const int* in_sizes, int n_in,
                              void* d_out, int out_size)
{
    const float* x  = (const float*)d_in[0];
    const float* Wq = (const float*)d_in[1];
    const float* bq = (const float*)d_in[2];
    const float* Wk = (const float*)d_in[3];
    const float* bk = (const float*)d_in[4];
    const float* Wv = (const float*)d_in[5];
    const float* bv = (const float*)d_in[6];
    float* out = (float*)d_out;

    __half* gxh; cudaGetSymbolAddress((void**)&gxh, g_xh);
    __half* gwh; cudaGetSymbolAddress((void**)&gwh, g_wh);

    to_half<<<(BB * SS * DD / 8 + 255) / 256, 256>>>(gxh, x, BB * SS * DD / 8);
    to_half<<<(DD * DD / 8 + 255) / 256, 256>>>(gwh,               Wq, DD * DD / 8);
    to_half<<<(DD * DD / 8 + 255) / 256, 256>>>(gwh + DD * DD,     Wk, DD * DD / 8);
    to_half<<<(DD * DD / 8 + 255) / 256, 256>>>(gwh + 2 * DD * DD, Wv, DD * DD / 8);

    dim3 gg(DD / 128, (BB * SS) / 128);   // (8, 128)
    qkv_gemm<<<gg, 256>>>(bq, 0);
    qkv_gemm<<<gg, 256>>>(bk, 1);
    qkv_gemm<<<gg, 256>>>(bv, 2);

    dim3 ga(SS / 64, BB * HH);            // (16, 256)
    attn_kernel<<<ga, 128>>>(out);
}